// round 2
// baseline (speedup 1.0000x reference)
#include <cuda_runtime.h>
#include <cuda_bf16.h>

#define NN 100000
#define EE 1600000
#define FIN 128
#define HID 64
#define NOUT 40

// Scratch (allocation-free rule: __device__ globals)
__device__ float g_dis[NN];
__device__ int   g_cnt[NN];
__device__ float g_h[(size_t)NN * HID];    // transformed features
__device__ float g_agg[(size_t)NN * HID];  // aggregated features

// ---------------- degree / normalization ----------------
__global__ void k_init_cnt() {
    int i = blockIdx.x * blockDim.x + threadIdx.x;
    if (i < NN) g_cnt[i] = 1;  // self-loop
}

__global__ void k_count(const int* __restrict__ dst) {
    int e = blockIdx.x * blockDim.x + threadIdx.x;
    if (e < EE) atomicAdd(&g_cnt[dst[e]], 1);
}

__global__ void k_dis() {
    int i = blockIdx.x * blockDim.x + threadIdx.x;
    if (i < NN) g_dis[i] = rsqrtf((float)g_cnt[i]);
}

// ---------------- GEMM: out[r,0:64] = act(in[r,0:K]) @ W[K,64] + b ----------------
// IN selects input: 0 = external ptr, 1 = g_agg. Output always g_h.
template<int K, int ROWS, bool RELU, int IN>
__global__ __launch_bounds__(256) void k_gemm(
    const float* __restrict__ in_ext, const float* __restrict__ W,
    const float* __restrict__ bias, int nrows)
{
    __shared__ float Xs[ROWS * K];
    __shared__ float Ws[K * 64];
    const float* in = (IN == 0) ? in_ext : g_agg;
    float* out = g_h;
    const int tid  = threadIdx.x;
    const int row0 = blockIdx.x * ROWS;

    // stage W
    for (int i = tid; i < K * 64 / 4; i += 256)
        ((float4*)Ws)[i] = ((const float4*)W)[i];
    // stage X (coalesced), with optional ReLU on input
    for (int i = tid; i < ROWS * K / 4; i += 256) {
        int r  = i / (K / 4);
        float4 v = make_float4(0.f, 0.f, 0.f, 0.f);
        if (row0 + r < nrows) {
            int c4 = i % (K / 4);
            v = ((const float4*)(in + (size_t)(row0 + r) * K))[c4];
        }
        if (RELU) {
            v.x = fmaxf(v.x, 0.f); v.y = fmaxf(v.y, 0.f);
            v.z = fmaxf(v.z, 0.f); v.w = fmaxf(v.w, 0.f);
        }
        ((float4*)Xs)[i] = v;
    }
    __syncthreads();

    const int cg = tid & 15;        // 16 col groups x 4 cols
    const int rg = tid >> 4;        // 16 row groups
    constexpr int RPT = ROWS / 16;  // rows per thread
    const int c = cg * 4;
    const int r = rg * RPT;

    float acc[RPT][4];
#pragma unroll
    for (int j = 0; j < RPT; ++j) { acc[j][0]=0.f; acc[j][1]=0.f; acc[j][2]=0.f; acc[j][3]=0.f; }

#pragma unroll 4
    for (int k = 0; k < K; ++k) {
        float4 w = *(const float4*)&Ws[k * 64 + c];
#pragma unroll
        for (int j = 0; j < RPT; ++j) {
            float x = Xs[(r + j) * K + k];
            acc[j][0] += x * w.x;
            acc[j][1] += x * w.y;
            acc[j][2] += x * w.z;
            acc[j][3] += x * w.w;
        }
    }

    float4 bb = *(const float4*)&bias[c];
#pragma unroll
    for (int j = 0; j < RPT; ++j) {
        if (row0 + r + j < nrows) {
            float4 o;
            o.x = acc[j][0] + bb.x; o.y = acc[j][1] + bb.y;
            o.z = acc[j][2] + bb.z; o.w = acc[j][3] + bb.w;
            *(float4*)(out + (size_t)(row0 + r + j) * 64 + c) = o;
        }
    }
}

// ---------------- self-loop init: agg[i] = h[i] * dis[i]^2 ----------------
__global__ __launch_bounds__(256) void k_self() {
    int idx = blockIdx.x * blockDim.x + threadIdx.x;   // one float4 per thread
    if (idx >= NN * (HID / 4)) return;
    int row = idx >> 4;  // HID/4 = 16 chunks per row
    float d = g_dis[row];
    float s = d * d;
    float4 v = ((const float4*)g_h)[idx];
    v.x *= s; v.y *= s; v.z *= s; v.w *= s;
    ((float4*)g_agg)[idx] = v;
}

// ---------------- edge scatter-add: agg[dst] += h[src] * dis[src]*dis[dst] ----------------
__device__ __forceinline__ void red_add_v4(float* p, float4 v) {
    asm volatile("red.global.add.v4.f32 [%0], {%1, %2, %3, %4};"
                 :: "l"(p), "f"(v.x), "f"(v.y), "f"(v.z), "f"(v.w)
                 : "memory");
}

__global__ __launch_bounds__(256) void k_edge(const int* __restrict__ src,
                                              const int* __restrict__ dst)
{
    int t = blockIdx.x * blockDim.x + threadIdx.x;
    int e = t >> 4;          // 16 threads per edge (64 floats)
    int c = t & 15;
    if (e >= EE) return;
    int s = __ldg(&src[e]);
    int d = __ldg(&dst[e]);
    float w = g_dis[s] * g_dis[d];
    float4 v = __ldg((const float4*)(g_h + (size_t)s * 64) + c);
    v.x *= w; v.y *= w; v.z *= w; v.w *= w;
    red_add_v4(g_agg + (size_t)d * 64 + c * 4, v);
}

// ---------------- output layer: out[r,0:40] = relu(agg[r,0:64]) @ Wout + bout ----------------
__global__ __launch_bounds__(256) void k_final(
    const float* __restrict__ W, const float* __restrict__ bias,
    float* __restrict__ out, int nrows)
{
    __shared__ float Xs[64 * 64];
    __shared__ float Ws[64 * NOUT];
    __shared__ float bs[NOUT];
    const int tid  = threadIdx.x;
    const int row0 = blockIdx.x * 64;

    for (int i = tid; i < 64 * NOUT / 4; i += 256)
        ((float4*)Ws)[i] = ((const float4*)W)[i];
    if (tid < NOUT) bs[tid] = bias[tid];
    for (int i = tid; i < 64 * 64 / 4; i += 256) {
        int r = i >> 4;
        float4 v = make_float4(0.f, 0.f, 0.f, 0.f);
        if (row0 + r < nrows) {
            int c4 = i & 15;
            v = ((const float4*)(g_agg + (size_t)(row0 + r) * 64))[c4];
        }
        v.x = fmaxf(v.x, 0.f); v.y = fmaxf(v.y, 0.f);
        v.z = fmaxf(v.z, 0.f); v.w = fmaxf(v.w, 0.f);
        ((float4*)Xs)[i] = v;
    }
    __syncthreads();

    for (int o = tid; o < 64 * NOUT; o += 256) {
        int r = o / NOUT, c = o % NOUT;
        float acc = 0.f;
#pragma unroll 8
        for (int k = 0; k < 64; ++k)
            acc += Xs[r * 64 + k] * Ws[k * NOUT + c];
        if (row0 + r < nrows)
            out[(size_t)(row0 + r) * NOUT + c] = acc + bs[c];
    }
}

// ---------------- launch: pure kernel launches only ----------------
extern "C" void kernel_launch(void* const* d_in, const int* in_sizes, int n_in,
                              void* d_out, int out_size)
{
    const float* x    = (const float*)d_in[0];
    const int*   ei   = (const int*)d_in[1];
    const int*   src  = ei;
    const int*   dst  = ei + EE;
    const float* W0   = (const float*)d_in[2];
    const float* b0   = (const float*)d_in[3];
    const float* W1   = (const float*)d_in[4];
    const float* b1   = (const float*)d_in[5];
    const float* W2   = (const float*)d_in[6];
    const float* b2   = (const float*)d_in[7];
    const float* Wout = (const float*)d_in[8];
    const float* bout = (const float*)d_in[9];
    float* out = (float*)d_out;

    const int nb_n    = (NN + 255) / 256;
    const int nb_e    = (EE + 255) / 256;
    const int nb_self = (NN * (HID / 4) + 255) / 256;
    const int nb_edge = (EE * 16 + 255) / 256;
    const int nb_g128 = (NN + 31) / 32;
    const int nb_g64  = (NN + 63) / 64;

    // normalization coefficients
    k_init_cnt<<<nb_n, 256>>>();
    k_count<<<nb_e, 256>>>(dst);
    k_dis<<<nb_n, 256>>>();

    // layer 1
    k_gemm<128, 32, false, 0><<<nb_g128, 256>>>(x, W0, b0, NN);
    k_self<<<nb_self, 256>>>();
    k_edge<<<nb_edge, 256>>>(src, dst);

    // layer 2 (ReLU fused into input staging)
    k_gemm<64, 64, true, 1><<<nb_g64, 256>>>(nullptr, W1, b1, NN);
    k_self<<<nb_self, 256>>>();
    k_edge<<<nb_edge, 256>>>(src, dst);

    // layer 3
    k_gemm<64, 64, true, 1><<<nb_g64, 256>>>(nullptr, W2, b2, NN);
    k_self<<<nb_self, 256>>>();
    k_edge<<<nb_edge, 256>>>(src, dst);

    // output layer
    k_final<<<nb_g64, 256>>>(Wout, bout, out, NN);
}

// round 6
// speedup vs baseline: 1.5109x; 1.5109x over previous
#include <cuda_runtime.h>
#include <cuda_bf16.h>

#define NN 100000
#define EE 1600000
#define FIN 128
#define HID 64
#define NOUT 40
#define SCAN_B 512
#define NBS ((NN + SCAN_B - 1) / SCAN_B)   // 196 blocks

// Scratch (allocation-free rule: __device__ globals)
__device__ float g_dis[NN];
__device__ int   g_cnt[NN];        // edge in-degree (excl self loop)
__device__ int   g_rowstart[NN];   // CSR row start
__device__ int   g_fill[NN];       // scatter fill counters
__device__ int   g_blocksum[256];  // scan partials
__device__ int   g_ssrc[EE];       // dst-sorted src indices
__device__ float g_h[(size_t)NN * HID];    // hs = dis * (XW+b)
__device__ float g_agg[(size_t)NN * HID];  // aggregated features

// ---------------- degree histogram ----------------
__global__ void k_zero() {
    int i = blockIdx.x * blockDim.x + threadIdx.x;
    if (i < NN) { g_cnt[i] = 0; g_fill[i] = 0; }
}

__global__ void k_count(const int* __restrict__ dst) {
    int e = blockIdx.x * blockDim.x + threadIdx.x;
    if (e < EE) atomicAdd(&g_cnt[dst[e]], 1);
}

__global__ void k_dis() {
    int i = blockIdx.x * blockDim.x + threadIdx.x;
    if (i < NN) g_dis[i] = rsqrtf((float)(g_cnt[i] + 1));  // +1 self loop
}

// ---------------- 2-level exclusive scan of g_cnt -> g_rowstart ----------------
__global__ __launch_bounds__(SCAN_B) void k_scan1() {
    __shared__ int sh[SCAN_B];
    int t = threadIdx.x;
    int i = blockIdx.x * SCAN_B + t;
    int v = (i < NN) ? g_cnt[i] : 0;
    sh[t] = v;
    __syncthreads();
#pragma unroll
    for (int o = 1; o < SCAN_B; o <<= 1) {
        int add = (t >= o) ? sh[t - o] : 0;
        __syncthreads();
        sh[t] += add;
        __syncthreads();
    }
    if (i < NN) g_rowstart[i] = sh[t] - v;          // exclusive
    if (t == SCAN_B - 1) g_blocksum[blockIdx.x] = sh[t];
}

__global__ __launch_bounds__(256) void k_scan2() {
    __shared__ int sh[256];
    int t = threadIdx.x;
    int v = (t < NBS) ? g_blocksum[t] : 0;
    sh[t] = v;
    __syncthreads();
#pragma unroll
    for (int o = 1; o < 256; o <<= 1) {
        int add = (t >= o) ? sh[t - o] : 0;
        __syncthreads();
        sh[t] += add;
        __syncthreads();
    }
    if (t < NBS) g_blocksum[t] = sh[t] - v;         // exclusive
}

__global__ __launch_bounds__(SCAN_B) void k_scan3() {
    int i = blockIdx.x * SCAN_B + threadIdx.x;
    if (i < NN) g_rowstart[i] += g_blocksum[blockIdx.x];
}

// ---------------- scatter edges into dst buckets ----------------
__global__ void k_scatter(const int* __restrict__ src, const int* __restrict__ dst) {
    int e = blockIdx.x * blockDim.x + threadIdx.x;
    if (e >= EE) return;
    int d = dst[e];
    int pos = g_rowstart[d] + atomicAdd(&g_fill[d], 1);
    g_ssrc[pos] = src[e];
}

// ---------------- GEMM: g_h[r] = dis[r] * (act(in[r]) @ W + b) ----------------
// IN: 0 = external ptr, 1 = g_agg.
template<int K, int ROWS, bool RELU, int IN>
__global__ __launch_bounds__(256) void k_gemm(
    const float* __restrict__ in_ext, const float* __restrict__ W,
    const float* __restrict__ bias, int nrows)
{
    __shared__ float Xs[ROWS * K];
    __shared__ float Ws[K * 64];
    const float* in = (IN == 0) ? in_ext : g_agg;
    const int tid  = threadIdx.x;
    const int row0 = blockIdx.x * ROWS;

    for (int i = tid; i < K * 64 / 4; i += 256)
        ((float4*)Ws)[i] = ((const float4*)W)[i];
    for (int i = tid; i < ROWS * K / 4; i += 256) {
        int r  = i / (K / 4);
        float4 v = make_float4(0.f, 0.f, 0.f, 0.f);
        if (row0 + r < nrows) {
            int c4 = i % (K / 4);
            v = ((const float4*)(in + (size_t)(row0 + r) * K))[c4];
        }
        if (RELU) {
            v.x = fmaxf(v.x, 0.f); v.y = fmaxf(v.y, 0.f);
            v.z = fmaxf(v.z, 0.f); v.w = fmaxf(v.w, 0.f);
        }
        ((float4*)Xs)[i] = v;
    }
    __syncthreads();

    const int cg = tid & 15;        // 16 col groups x 4 cols
    const int rg = tid >> 4;        // 16 row groups
    constexpr int RPT = ROWS / 16;
    const int c = cg * 4;
    const int r = rg * RPT;

    float acc[RPT][4];
#pragma unroll
    for (int j = 0; j < RPT; ++j) { acc[j][0]=0.f; acc[j][1]=0.f; acc[j][2]=0.f; acc[j][3]=0.f; }

#pragma unroll 4
    for (int kk = 0; kk < K; kk += 4) {
        float4 w0 = *(const float4*)&Ws[(kk + 0) * 64 + c];
        float4 w1 = *(const float4*)&Ws[(kk + 1) * 64 + c];
        float4 w2 = *(const float4*)&Ws[(kk + 2) * 64 + c];
        float4 w3 = *(const float4*)&Ws[(kk + 3) * 64 + c];
#pragma unroll
        for (int j = 0; j < RPT; ++j) {
            float4 xv = *(const float4*)&Xs[(r + j) * K + kk];
            acc[j][0] += xv.x * w0.x + xv.y * w1.x + xv.z * w2.x + xv.w * w3.x;
            acc[j][1] += xv.x * w0.y + xv.y * w1.y + xv.z * w2.y + xv.w * w3.y;
            acc[j][2] += xv.x * w0.z + xv.y * w1.z + xv.z * w2.z + xv.w * w3.z;
            acc[j][3] += xv.x * w0.w + xv.y * w1.w + xv.z * w2.w + xv.w * w3.w;
        }
    }

    float4 bb = *(const float4*)&bias[c];
#pragma unroll
    for (int j = 0; j < RPT; ++j) {
        int row = row0 + r + j;
        if (row < nrows) {
            float s = g_dis[row];
            float4 o;
            o.x = (acc[j][0] + bb.x) * s; o.y = (acc[j][1] + bb.y) * s;
            o.z = (acc[j][2] + bb.z) * s; o.w = (acc[j][3] + bb.w) * s;
            *(float4*)(g_h + (size_t)row * 64 + c) = o;
        }
    }
}

// ---------------- CSR gather: agg[d] = dis[d] * (hs[d] + sum_src hs[src]) ----------------
__global__ __launch_bounds__(256) void k_gather() {
    int t = blockIdx.x * blockDim.x + threadIdx.x;
    int node = t >> 4;          // 16 threads per node
    int c = t & 15;
    if (node >= NN) return;
    const float4* hs = (const float4*)g_h;
    float4 acc = hs[(size_t)node * 16 + c];   // self term
    int beg = g_rowstart[node];
    int deg = g_cnt[node];
    int end = beg + deg;
    int e = beg;
    // unroll 4 for MLP
    for (; e + 4 <= end; e += 4) {
        int s0 = __ldg(&g_ssrc[e + 0]);
        int s1 = __ldg(&g_ssrc[e + 1]);
        int s2 = __ldg(&g_ssrc[e + 2]);
        int s3 = __ldg(&g_ssrc[e + 3]);
        float4 v0 = __ldg(hs + (size_t)s0 * 16 + c);
        float4 v1 = __ldg(hs + (size_t)s1 * 16 + c);
        float4 v2 = __ldg(hs + (size_t)s2 * 16 + c);
        float4 v3 = __ldg(hs + (size_t)s3 * 16 + c);
        acc.x += (v0.x + v1.x) + (v2.x + v3.x);
        acc.y += (v0.y + v1.y) + (v2.y + v3.y);
        acc.z += (v0.z + v1.z) + (v2.z + v3.z);
        acc.w += (v0.w + v1.w) + (v2.w + v3.w);
    }
    for (; e < end; ++e) {
        int s = __ldg(&g_ssrc[e]);
        float4 v = __ldg(hs + (size_t)s * 16 + c);
        acc.x += v.x; acc.y += v.y; acc.z += v.z; acc.w += v.w;
    }
    float d = g_dis[node];
    acc.x *= d; acc.y *= d; acc.z *= d; acc.w *= d;
    ((float4*)g_agg)[(size_t)node * 16 + c] = acc;
}

// ---------------- output layer: out[r] = relu(agg[r]) @ Wout + bout ----------------
__global__ __launch_bounds__(256) void k_final(
    const float* __restrict__ W, const float* __restrict__ bias,
    float* __restrict__ out, int nrows)
{
    __shared__ float Xs[64 * 64];
    __shared__ float Ws[64 * NOUT];
    __shared__ float bs[NOUT];
    const int tid  = threadIdx.x;
    const int row0 = blockIdx.x * 64;

    for (int i = tid; i < 64 * NOUT / 4; i += 256)
        ((float4*)Ws)[i] = ((const float4*)W)[i];
    if (tid < NOUT) bs[tid] = bias[tid];
    for (int i = tid; i < 64 * 64 / 4; i += 256) {
        int r = i >> 4;
        float4 v = make_float4(0.f, 0.f, 0.f, 0.f);
        if (row0 + r < nrows) {
            int c4 = i & 15;
            v = ((const float4*)(g_agg + (size_t)(row0 + r) * 64))[c4];
        }
        v.x = fmaxf(v.x, 0.f); v.y = fmaxf(v.y, 0.f);
        v.z = fmaxf(v.z, 0.f); v.w = fmaxf(v.w, 0.f);
        ((float4*)Xs)[i] = v;
    }
    __syncthreads();

    for (int o = tid; o < 64 * NOUT; o += 256) {
        int r = o / NOUT, c = o % NOUT;
        float acc = 0.f;
#pragma unroll 8
        for (int k = 0; k < 64; ++k)
            acc += Xs[r * 64 + k] * Ws[k * NOUT + c];
        if (row0 + r < nrows)
            out[(size_t)(row0 + r) * NOUT + c] = acc + bs[c];
    }
}

// ---------------- launch: pure kernel launches only ----------------
extern "C" void kernel_launch(void* const* d_in, const int* in_sizes, int n_in,
                              void* d_out, int out_size)
{
    const float* x    = (const float*)d_in[0];
    const int*   ei   = (const int*)d_in[1];
    const int*   src  = ei;
    const int*   dst  = ei + EE;
    const float* W0   = (const float*)d_in[2];
    const float* b0   = (const float*)d_in[3];
    const float* W1   = (const float*)d_in[4];
    const float* b1   = (const float*)d_in[5];
    const float* W2   = (const float*)d_in[6];
    const float* b2   = (const float*)d_in[7];
    const float* Wout = (const float*)d_in[8];
    const float* bout = (const float*)d_in[9];
    float* out = (float*)d_out;

    const int nb_n      = (NN + 255) / 256;
    const int nb_e      = (EE + 255) / 256;
    const int nb_gather = (NN * 16 + 255) / 256;
    const int nb_g128   = (NN + 31) / 32;
    const int nb_g64    = (NN + 63) / 64;

    // ---- CSR build + normalization ----
    k_zero<<<nb_n, 256>>>();
    k_count<<<nb_e, 256>>>(dst);
    k_dis<<<nb_n, 256>>>();
    k_scan1<<<NBS, SCAN_B>>>();
    k_scan2<<<1, 256>>>();
    k_scan3<<<NBS, SCAN_B>>>();
    k_scatter<<<nb_e, 256>>>(src, dst);

    // ---- layer 1 ----
    k_gemm<128, 32, false, 0><<<nb_g128, 256>>>(x, W0, b0, NN);
    k_gather<<<nb_gather, 256>>>();

    // ---- layer 2 ----
    k_gemm<64, 64, true, 1><<<nb_g64, 256>>>(nullptr, W1, b1, NN);
    k_gather<<<nb_gather, 256>>>();

    // ---- layer 3 ----
    k_gemm<64, 64, true, 1><<<nb_g64, 256>>>(nullptr, W2, b2, NN);
    k_gather<<<nb_gather, 256>>>();

    // ---- output ----
    k_final<<<nb_g64, 256>>>(Wout, bout, out, NN);
}